// round 3
// baseline (speedup 1.0000x reference)
#include <cuda_runtime.h>

#define NN 50000
#define NE 800000
#define INC 256
#define HC  128

// Scratch (no cudaMalloc allowed)
__device__ float g_h[(size_t)NN * HC];
__device__ float g_deg[NN];
__device__ float g_dis[NN];

// ---------------------------------------------------------------------------
// Degree: init to 1.0 (self-loop weight), accumulate edge weights at col
// ---------------------------------------------------------------------------
__global__ void k_deg_init() {
    int i = blockIdx.x * blockDim.x + threadIdx.x;
    if (i < NN) g_deg[i] = 1.0f;
}

__global__ void k_deg_acc(const int* __restrict__ ei,
                          const float* __restrict__ ew) {
    int e = blockIdx.x * blockDim.x + threadIdx.x;
    if (e < NE) {
        int c = ei[NE + e];
        atomicAdd(&g_deg[c], ew[e]);
    }
}

__global__ void k_dis() {
    int i = blockIdx.x * blockDim.x + threadIdx.x;
    if (i < NN) {
        float d = g_deg[i];
        g_dis[i] = d > 0.0f ? rsqrtf(d) : 0.0f;
    }
}

// ---------------------------------------------------------------------------
// GEMM: h = x @ W  (fp32, 128x128x16 tiles, 8x8 register tiles)
// Epilogue also writes the self-loop contribution out[i] = h[i]*dis[i]^2
// ---------------------------------------------------------------------------
#define BM 128
#define BN 128
#define BK 16

__global__ __launch_bounds__(256, 2)
void k_gemm(const float* __restrict__ x, const float* __restrict__ W,
            float* __restrict__ out) {
    __shared__ float xs[BM][BK + 1];   // +1 pad: conflict-free column reads
    __shared__ float ws[BK][BN];

    int tid = threadIdx.x;
    int tr = tid >> 4;     // 0..15 (row group)
    int tc = tid & 15;     // 0..15 (col group)
    int rowBase = blockIdx.x * BM;

    float acc[8][8];
#pragma unroll
    for (int i = 0; i < 8; i++)
#pragma unroll
        for (int j = 0; j < 8; j++) acc[i][j] = 0.0f;

    for (int k0 = 0; k0 < INC; k0 += BK) {
        // x tile: 128 rows x 16 k = 512 float4 loads
#pragma unroll
        for (int l = 0; l < 2; l++) {
            int idx = tid + l * 256;
            int r  = idx >> 2;
            int kq = idx & 3;
            float4 v = make_float4(0.f, 0.f, 0.f, 0.f);
            int gr = rowBase + r;
            if (gr < NN)
                v = *reinterpret_cast<const float4*>(&x[(size_t)gr * INC + k0 + kq * 4]);
            xs[r][kq * 4 + 0] = v.x;
            xs[r][kq * 4 + 1] = v.y;
            xs[r][kq * 4 + 2] = v.z;
            xs[r][kq * 4 + 3] = v.w;
        }
        // W tile: 16 k x 128 cols = 512 float4 loads
#pragma unroll
        for (int l = 0; l < 2; l++) {
            int idx = tid + l * 256;
            int kr = idx >> 5;
            int cq = idx & 31;
            float4 v = *reinterpret_cast<const float4*>(&W[(size_t)(k0 + kr) * HC + cq * 4]);
            *reinterpret_cast<float4*>(&ws[kr][cq * 4]) = v;
        }
        __syncthreads();

#pragma unroll
        for (int k = 0; k < BK; k++) {
            float a[8], bl[8];
#pragma unroll
            for (int i = 0; i < 8; i++) a[i] = xs[tr * 8 + i][k];
            float4 b0 = *reinterpret_cast<const float4*>(&ws[k][tc * 8]);
            float4 b1 = *reinterpret_cast<const float4*>(&ws[k][tc * 8 + 4]);
            bl[0] = b0.x; bl[1] = b0.y; bl[2] = b0.z; bl[3] = b0.w;
            bl[4] = b1.x; bl[5] = b1.y; bl[6] = b1.z; bl[7] = b1.w;
#pragma unroll
            for (int i = 0; i < 8; i++)
#pragma unroll
                for (int j = 0; j < 8; j++)
                    acc[i][j] = fmaf(a[i], bl[j], acc[i][j]);
        }
        __syncthreads();
    }

    // Epilogue: store h and self-loop term to out
#pragma unroll
    for (int i = 0; i < 8; i++) {
        int gr = rowBase + tr * 8 + i;
        if (gr >= NN) continue;
        float s  = g_dis[gr];
        float s2 = s * s;
        size_t base = (size_t)gr * HC + tc * 8;
#pragma unroll
        for (int j = 0; j < 8; j += 4) {
            float4 v = make_float4(acc[i][j], acc[i][j + 1], acc[i][j + 2], acc[i][j + 3]);
            *reinterpret_cast<float4*>(&g_h[base + j]) = v;
            float4 o = make_float4(v.x * s2, v.y * s2, v.z * s2, v.w * s2);
            *reinterpret_cast<float4*>(&out[base + j]) = o;
        }
    }
}

// ---------------------------------------------------------------------------
// Scatter: one warp per edge, float4 gather + float4 vector atomicAdd
// ---------------------------------------------------------------------------
__global__ void k_scatter(const int* __restrict__ ei,
                          const float* __restrict__ ew,
                          float* __restrict__ out) {
    int warp = (blockIdx.x * blockDim.x + threadIdx.x) >> 5;
    int lane = threadIdx.x & 31;
    if (warp >= NE) return;

    int r = ei[warp];
    int c = ei[NE + warp];
    float nrm = g_dis[r] * ew[warp] * g_dis[c];

    float4 v = *reinterpret_cast<const float4*>(&g_h[(size_t)r * HC + lane * 4]);
    v.x *= nrm; v.y *= nrm; v.z *= nrm; v.w *= nrm;

    float* p = &out[(size_t)c * HC + lane * 4];
#if __CUDA_ARCH__ >= 900
    atomicAdd(reinterpret_cast<float4*>(p), v);   // red.global.v4.f32
#else
    atomicAdd(p + 0, v.x);
    atomicAdd(p + 1, v.y);
    atomicAdd(p + 2, v.z);
    atomicAdd(p + 3, v.w);
#endif
}

// ---------------------------------------------------------------------------
// Final: out = PReLU(out + b)
// ---------------------------------------------------------------------------
__global__ void k_final(float* __restrict__ out, const float* __restrict__ b,
                        const float* __restrict__ alpha) {
    int i = blockIdx.x * blockDim.x + threadIdx.x;
    if (i >= NN * HC / 4) return;
    int c4 = i & 31;   // HC/4 = 32 float4 per row
    float4 v  = reinterpret_cast<float4*>(out)[i];
    float4 bb = reinterpret_cast<const float4*>(b)[c4];
    float4 aa = reinterpret_cast<const float4*>(alpha)[c4];
    v.x += bb.x; v.y += bb.y; v.z += bb.z; v.w += bb.w;
    v.x = v.x >= 0.f ? v.x : aa.x * v.x;
    v.y = v.y >= 0.f ? v.y : aa.y * v.y;
    v.z = v.z >= 0.f ? v.z : aa.z * v.z;
    v.w = v.w >= 0.f ? v.w : aa.w * v.w;
    reinterpret_cast<float4*>(out)[i] = v;
}

// ---------------------------------------------------------------------------
extern "C" void kernel_launch(void* const* d_in, const int* in_sizes, int n_in,
                              void* d_out, int out_size) {
    const float* x  = (const float*)d_in[0];
    const int*   ei = (const int*)d_in[1];     // int32: JAX x64-disabled downcast
    const float* ew = (const float*)d_in[2];
    const float* W  = (const float*)d_in[3];
    const float* b  = (const float*)d_in[4];
    const float* al = (const float*)d_in[5];
    float* out = (float*)d_out;

    k_deg_init<<<(NN + 255) / 256, 256>>>();
    k_deg_acc<<<(NE + 255) / 256, 256>>>(ei, ew);
    k_dis<<<(NN + 255) / 256, 256>>>();
    k_gemm<<<(NN + BM - 1) / BM, 256>>>(x, W, out);
    k_scatter<<<(NE + 7) / 8, 256>>>(ei, ew, out);   // 8 warps/block, 1 edge/warp
    k_final<<<((NN * HC / 4) + 255) / 256, 256>>>(out, b, al);
}

// round 7
// speedup vs baseline: 1.4912x; 1.4912x over previous
#include <cuda_runtime.h>

#define NN 50000
#define NE 800000
#define INC 256
#define HC  128

// Scratch (no cudaMalloc allowed)
__device__ float g_h[(size_t)NN * HC];
__device__ float g_deg[NN];
__device__ float g_dis[NN];
__device__ int   g_cnt[NN];
__device__ int   g_off[NN + 1];
__device__ int   g_cursor[NN];
__device__ int   g_csr_row[NE];
__device__ float g_csr_nrm[NE];

// ---------------------------------------------------------------------------
// Degree init (self-loop weight 1) + zero histogram
// ---------------------------------------------------------------------------
__global__ void k_deg_init() {
    int i = blockIdx.x * blockDim.x + threadIdx.x;
    if (i < NN) { g_deg[i] = 1.0f; g_cnt[i] = 0; }
}

// Degree accumulate + destination histogram (merged edge pass)
__global__ void k_deg_count(const int* __restrict__ ei,
                            const float* __restrict__ ew) {
    int e = blockIdx.x * blockDim.x + threadIdx.x;
    if (e < NE) {
        int c = ei[NE + e];
        atomicAdd(&g_deg[c], ew[e]);
        atomicAdd(&g_cnt[c], 1);
    }
}

__global__ void k_dis() {
    int i = blockIdx.x * blockDim.x + threadIdx.x;
    if (i < NN) {
        float d = g_deg[i];
        g_dis[i] = d > 0.0f ? rsqrtf(d) : 0.0f;
    }
}

// ---------------------------------------------------------------------------
// Exclusive prefix sum over g_cnt -> g_off (single block, warp-shuffle scan)
// ---------------------------------------------------------------------------
__global__ void k_scan() {
    __shared__ int warpsum[32];
    __shared__ int s_carry;
    int tid = threadIdx.x, lane = tid & 31, wid = tid >> 5;
    if (tid == 0) s_carry = 0;
    __syncthreads();

    for (int base = 0; base < NN; base += 1024) {
        int i = base + tid;
        int v = (i < NN) ? g_cnt[i] : 0;
        int x = v;
#pragma unroll
        for (int o = 1; o < 32; o <<= 1) {
            int t = __shfl_up_sync(0xFFFFFFFFu, x, o);
            if (lane >= o) x += t;
        }
        if (lane == 31) warpsum[wid] = x;
        __syncthreads();
        if (wid == 0) {
            int w = warpsum[lane];
#pragma unroll
            for (int o = 1; o < 32; o <<= 1) {
                int t = __shfl_up_sync(0xFFFFFFFFu, w, o);
                if (lane >= o) w += t;
            }
            warpsum[lane] = w;
        }
        __syncthreads();
        int pre   = (wid > 0) ? warpsum[wid - 1] : 0;
        int carry = s_carry;
        int excl  = carry + pre + x - v;
        if (i < NN) { g_off[i] = excl; g_cursor[i] = excl; }
        __syncthreads();
        if (tid == 1023) s_carry = carry + warpsum[31];
        __syncthreads();
    }
    if (threadIdx.x == 0) g_off[NN] = s_carry;
}

// ---------------------------------------------------------------------------
// Fill CSR buckets: edge row id + precomputed norm per edge
// ---------------------------------------------------------------------------
__global__ void k_fill(const int* __restrict__ ei,
                       const float* __restrict__ ew) {
    int e = blockIdx.x * blockDim.x + threadIdx.x;
    if (e < NE) {
        int r = ei[e];
        int c = ei[NE + e];
        int pos = atomicAdd(&g_cursor[c], 1);
        g_csr_row[pos] = r;
        g_csr_nrm[pos] = g_dis[r] * ew[e] * g_dis[c];
    }
}

// ---------------------------------------------------------------------------
// GEMM: h = x @ W  (fp32, 128x128x16 tiles, 8x8 register tiles)
// Epilogue also writes the self-loop contribution out[i] = h[i]*dis[i]^2
// ---------------------------------------------------------------------------
#define BM 128
#define BN 128
#define BK 16

__global__ __launch_bounds__(256, 2)
void k_gemm(const float* __restrict__ x, const float* __restrict__ W,
            float* __restrict__ out) {
    __shared__ float xs[BM][BK + 1];
    __shared__ float ws[BK][BN];

    int tid = threadIdx.x;
    int tr = tid >> 4;
    int tc = tid & 15;
    int rowBase = blockIdx.x * BM;

    float acc[8][8];
#pragma unroll
    for (int i = 0; i < 8; i++)
#pragma unroll
        for (int j = 0; j < 8; j++) acc[i][j] = 0.0f;

    for (int k0 = 0; k0 < INC; k0 += BK) {
#pragma unroll
        for (int l = 0; l < 2; l++) {
            int idx = tid + l * 256;
            int r  = idx >> 2;
            int kq = idx & 3;
            float4 v = make_float4(0.f, 0.f, 0.f, 0.f);
            int gr = rowBase + r;
            if (gr < NN)
                v = *reinterpret_cast<const float4*>(&x[(size_t)gr * INC + k0 + kq * 4]);
            xs[r][kq * 4 + 0] = v.x;
            xs[r][kq * 4 + 1] = v.y;
            xs[r][kq * 4 + 2] = v.z;
            xs[r][kq * 4 + 3] = v.w;
        }
#pragma unroll
        for (int l = 0; l < 2; l++) {
            int idx = tid + l * 256;
            int kr = idx >> 5;
            int cq = idx & 31;
            float4 v = *reinterpret_cast<const float4*>(&W[(size_t)(k0 + kr) * HC + cq * 4]);
            *reinterpret_cast<float4*>(&ws[kr][cq * 4]) = v;
        }
        __syncthreads();

#pragma unroll
        for (int k = 0; k < BK; k++) {
            float a[8], bl[8];
#pragma unroll
            for (int i = 0; i < 8; i++) a[i] = xs[tr * 8 + i][k];
            float4 b0 = *reinterpret_cast<const float4*>(&ws[k][tc * 8]);
            float4 b1 = *reinterpret_cast<const float4*>(&ws[k][tc * 8 + 4]);
            bl[0] = b0.x; bl[1] = b0.y; bl[2] = b0.z; bl[3] = b0.w;
            bl[4] = b1.x; bl[5] = b1.y; bl[6] = b1.z; bl[7] = b1.w;
#pragma unroll
            for (int i = 0; i < 8; i++)
#pragma unroll
                for (int j = 0; j < 8; j++)
                    acc[i][j] = fmaf(a[i], bl[j], acc[i][j]);
        }
        __syncthreads();
    }

#pragma unroll
    for (int i = 0; i < 8; i++) {
        int gr = rowBase + tr * 8 + i;
        if (gr >= NN) continue;
        float s  = g_dis[gr];
        float s2 = s * s;
        size_t base = (size_t)gr * HC + tc * 8;
#pragma unroll
        for (int j = 0; j < 8; j += 4) {
            float4 v = make_float4(acc[i][j], acc[i][j + 1], acc[i][j + 2], acc[i][j + 3]);
            *reinterpret_cast<float4*>(&g_h[base + j]) = v;
            float4 o = make_float4(v.x * s2, v.y * s2, v.z * s2, v.w * s2);
            *reinterpret_cast<float4*>(&out[base + j]) = o;
        }
    }
}

// ---------------------------------------------------------------------------
// Aggregate: one warp per destination node, gather h[row]*nrm over CSR bucket.
// No atomics (exclusive ownership). Folds bias + PReLU epilogue.
// ---------------------------------------------------------------------------
__global__ __launch_bounds__(256)
void k_agg(float* __restrict__ out, const float* __restrict__ b,
           const float* __restrict__ alpha) {
    int node = blockIdx.x * (blockDim.x >> 5) + (threadIdx.x >> 5);
    int lane = threadIdx.x & 31;
    if (node >= NN) return;

    int s = g_off[node];
    int e = g_off[node + 1];

    // start from self-loop term written by gemm epilogue
    float4 acc = *reinterpret_cast<const float4*>(&out[(size_t)node * HC + lane * 4]);

    int j = s;
    // unroll by 2 for memory-level parallelism
    for (; j + 1 < e; j += 2) {
        int   r0 = g_csr_row[j],     r1 = g_csr_row[j + 1];
        float n0 = g_csr_nrm[j],     n1 = g_csr_nrm[j + 1];
        float4 v0 = *reinterpret_cast<const float4*>(&g_h[(size_t)r0 * HC + lane * 4]);
        float4 v1 = *reinterpret_cast<const float4*>(&g_h[(size_t)r1 * HC + lane * 4]);
        acc.x = fmaf(v0.x, n0, acc.x); acc.y = fmaf(v0.y, n0, acc.y);
        acc.z = fmaf(v0.z, n0, acc.z); acc.w = fmaf(v0.w, n0, acc.w);
        acc.x = fmaf(v1.x, n1, acc.x); acc.y = fmaf(v1.y, n1, acc.y);
        acc.z = fmaf(v1.z, n1, acc.z); acc.w = fmaf(v1.w, n1, acc.w);
    }
    if (j < e) {
        int   r0 = g_csr_row[j];
        float n0 = g_csr_nrm[j];
        float4 v0 = *reinterpret_cast<const float4*>(&g_h[(size_t)r0 * HC + lane * 4]);
        acc.x = fmaf(v0.x, n0, acc.x); acc.y = fmaf(v0.y, n0, acc.y);
        acc.z = fmaf(v0.z, n0, acc.z); acc.w = fmaf(v0.w, n0, acc.w);
    }

    // bias + PReLU
    float4 bb = *reinterpret_cast<const float4*>(&b[lane * 4]);
    float4 aa = *reinterpret_cast<const float4*>(&alpha[lane * 4]);
    acc.x += bb.x; acc.y += bb.y; acc.z += bb.z; acc.w += bb.w;
    acc.x = acc.x >= 0.f ? acc.x : aa.x * acc.x;
    acc.y = acc.y >= 0.f ? acc.y : aa.y * acc.y;
    acc.z = acc.z >= 0.f ? acc.z : aa.z * acc.z;
    acc.w = acc.w >= 0.f ? acc.w : aa.w * acc.w;
    *reinterpret_cast<float4*>(&out[(size_t)node * HC + lane * 4]) = acc;
}

// ---------------------------------------------------------------------------
extern "C" void kernel_launch(void* const* d_in, const int* in_sizes, int n_in,
                              void* d_out, int out_size) {
    const float* x  = (const float*)d_in[0];
    const int*   ei = (const int*)d_in[1];     // int32 (JAX x64-disabled downcast)
    const float* ew = (const float*)d_in[2];
    const float* W  = (const float*)d_in[3];
    const float* b  = (const float*)d_in[4];
    const float* al = (const float*)d_in[5];
    float* out = (float*)d_out;

    k_deg_init<<<(NN + 255) / 256, 256>>>();
    k_deg_count<<<(NE + 255) / 256, 256>>>(ei, ew);
    k_dis<<<(NN + 255) / 256, 256>>>();
    k_scan<<<1, 1024>>>();
    k_fill<<<(NE + 255) / 256, 256>>>(ei, ew);
    k_gemm<<<(NN + BM - 1) / BM, 256>>>(x, W, out);
    k_agg<<<(NN * 32 + 255) / 256, 256>>>(out, b, al);
}

// round 9
// speedup vs baseline: 2.0247x; 1.3577x over previous
#include <cuda_runtime.h>
#include <cstdint>

#define NN 50000
#define NE 800000
#define INC 256
#define HC  128

// Scratch (no cudaMalloc allowed)
__device__ float g_h[(size_t)NN * HC];
__device__ float g_deg[NN];
__device__ float g_dis[NN];
__device__ int   g_cnt[NN];
__device__ int   g_off[NN + 1];
__device__ int   g_cursor[NN];
__device__ int   g_csr_row[NE];
__device__ float g_csr_nrm[NE];

#define SCAN_B 1024
#define NBLK ((NN + SCAN_B - 1) / SCAN_B)   // 49
__device__ int g_blkoff[64];

// ---------------------------------------------------------------------------
__global__ void k_deg_init() {
    int i = blockIdx.x * blockDim.x + threadIdx.x;
    if (i < NN) { g_deg[i] = 1.0f; g_cnt[i] = 0; }
}

__global__ void k_deg_count(const int* __restrict__ ei,
                            const float* __restrict__ ew) {
    int e = blockIdx.x * blockDim.x + threadIdx.x;
    if (e < NE) {
        int c = ei[NE + e];
        atomicAdd(&g_deg[c], ew[e]);
        atomicAdd(&g_cnt[c], 1);
    }
}

// ---------------------------------------------------------------------------
// Scan phase 1: per-block exclusive scan of g_cnt + block totals.
// Also computes g_dis (same index space, g_deg is final here).
// ---------------------------------------------------------------------------
__global__ void k_scan_blk() {
    __shared__ int warpsum[32];
    int tid = threadIdx.x, lane = tid & 31, wid = tid >> 5;
    int i = blockIdx.x * SCAN_B + tid;

    if (i < NN) {
        float d = g_deg[i];
        g_dis[i] = d > 0.0f ? rsqrtf(d) : 0.0f;
    }

    int v = (i < NN) ? g_cnt[i] : 0;
    int x = v;
#pragma unroll
    for (int o = 1; o < 32; o <<= 1) {
        int t = __shfl_up_sync(0xFFFFFFFFu, x, o);
        if (lane >= o) x += t;
    }
    if (lane == 31) warpsum[wid] = x;
    __syncthreads();
    if (wid == 0) {
        int w = warpsum[lane];
#pragma unroll
        for (int o = 1; o < 32; o <<= 1) {
            int t = __shfl_up_sync(0xFFFFFFFFu, w, o);
            if (lane >= o) w += t;
        }
        warpsum[lane] = w;
    }
    __syncthreads();
    int pre = (wid > 0) ? warpsum[wid - 1] : 0;
    if (i < NN) g_off[i] = pre + x - v;           // block-local exclusive
    if (tid == 0) g_blkoff[blockIdx.x] = warpsum[31];  // block total (temp)
}

// Scan phase 2: one warp exclusive-scans the (≤64) block totals.
__global__ void k_scan_top() {
    int lane = threadIdx.x;   // 32 threads
    int v0 = (lane < NBLK) ? g_blkoff[lane] : 0;
    int v1 = (lane + 32 < NBLK) ? g_blkoff[lane + 32] : 0;
    int x0 = v0;
#pragma unroll
    for (int o = 1; o < 32; o <<= 1) {
        int t = __shfl_up_sync(0xFFFFFFFFu, x0, o);
        if (lane >= o) x0 += t;
    }
    int tot0 = __shfl_sync(0xFFFFFFFFu, x0, 31);
    int x1 = v1;
#pragma unroll
    for (int o = 1; o < 32; o <<= 1) {
        int t = __shfl_up_sync(0xFFFFFFFFu, x1, o);
        if (lane >= o) x1 += t;
    }
    g_blkoff[lane]      = x0 - v0;                // exclusive
    g_blkoff[lane + 32] = tot0 + x1 - v1;
    if (lane == 31) g_off[NN] = tot0 + __shfl_sync(0xFFFFFFFFu, x1, 31);
}

// Scan phase 3: add block offsets, init cursors.
__global__ void k_scan_add() {
    int i = blockIdx.x * SCAN_B + threadIdx.x;
    if (i < NN) {
        int o = g_off[i] + g_blkoff[blockIdx.x];
        g_off[i] = o;
        g_cursor[i] = o;
    }
}

// ---------------------------------------------------------------------------
__global__ void k_fill(const int* __restrict__ ei,
                       const float* __restrict__ ew) {
    int e = blockIdx.x * blockDim.x + threadIdx.x;
    if (e < NE) {
        int r = ei[e];
        int c = ei[NE + e];
        int pos = atomicAdd(&g_cursor[c], 1);
        g_csr_row[pos] = r;
        g_csr_nrm[pos] = g_dis[r] * ew[e] * g_dis[c];
    }
}

// ---------------------------------------------------------------------------
// GEMM: h = x @ W  (fp32, 128x128x16 tiles, 8x8 reg tiles, double-buffered)
//   x tile stored k-major (xs[BK][BM]) -> A-reads are 2x LDS.128 broadcasts
//   W tile loaded via cp.async; x tile prefetched through registers
// Epilogue writes h and the self-loop term out[i] = h[i]*dis[i]^2
// ---------------------------------------------------------------------------
#define BM 128
#define BN 128
#define BK 16
#define NT (INC / BK)

__device__ __forceinline__ void cp16(void* s, const void* g) {
    uint32_t sa = (uint32_t)__cvta_generic_to_shared(s);
    asm volatile("cp.async.cg.shared.global [%0], [%1], 16;\n" :: "r"(sa), "l"(g));
}

__global__ __launch_bounds__(256, 2)
void k_gemm(const float* __restrict__ x, const float* __restrict__ W,
            float* __restrict__ out) {
    __shared__ float xs[2][BK][BM];   // 16 KB
    __shared__ float ws[2][BK][BN];   // 16 KB

    int tid = threadIdx.x;
    int tr = tid >> 4;
    int tc = tid & 15;
    int rowBase = blockIdx.x * BM;

    // x loader mapping: 512 float4 = (r 0..127) x (kq 0..3)
    int xr0 = tid >> 1;                     // via idx = tid + l*256: r = idx>>2
    (void)xr0;

    float4 xreg[2];

    float acc[8][8];
#pragma unroll
    for (int i = 0; i < 8; i++)
#pragma unroll
        for (int j = 0; j < 8; j++) acc[i][j] = 0.0f;

    // --- loaders ---
    auto ldx = [&](int t) {
#pragma unroll
        for (int l = 0; l < 2; l++) {
            int idx = tid + l * 256;
            int r  = idx >> 2;
            int kq = idx & 3;
            int gr = rowBase + r;
            float4 v = make_float4(0.f, 0.f, 0.f, 0.f);
            if (gr < NN)
                v = *reinterpret_cast<const float4*>(&x[(size_t)gr * INC + t * BK + kq * 4]);
            xreg[l] = v;
        }
    };
    auto stx = [&](int buf) {
#pragma unroll
        for (int l = 0; l < 2; l++) {
            int idx = tid + l * 256;
            int r  = idx >> 2;
            int kq = idx & 3;
            xs[buf][kq * 4 + 0][r] = xreg[l].x;
            xs[buf][kq * 4 + 1][r] = xreg[l].y;
            xs[buf][kq * 4 + 2][r] = xreg[l].z;
            xs[buf][kq * 4 + 3][r] = xreg[l].w;
        }
    };
    auto ldw = [&](int t, int buf) {
#pragma unroll
        for (int l = 0; l < 2; l++) {
            int idx = tid + l * 256;
            int kr = idx >> 5;
            int cq = idx & 31;
            cp16(&ws[buf][kr][cq * 4], &W[(size_t)(t * BK + kr) * HC + cq * 4]);
        }
        asm volatile("cp.async.commit_group;\n");
    };

    // prologue: tile 0
    ldx(0);
    ldw(0, 0);
    stx(0);
    asm volatile("cp.async.wait_group 0;\n");
    __syncthreads();

#pragma unroll 2
    for (int t = 0; t < NT; t++) {
        int cur = t & 1, nxt = cur ^ 1;
        bool more = (t + 1 < NT);
        if (more) { ldx(t + 1); ldw(t + 1, nxt); }

#pragma unroll
        for (int k = 0; k < BK; k++) {
            float4 a0 = *reinterpret_cast<const float4*>(&xs[cur][k][tr * 8]);
            float4 a1 = *reinterpret_cast<const float4*>(&xs[cur][k][tr * 8 + 4]);
            float4 b0 = *reinterpret_cast<const float4*>(&ws[cur][k][tc * 8]);
            float4 b1 = *reinterpret_cast<const float4*>(&ws[cur][k][tc * 8 + 4]);
            float a[8] = {a0.x, a0.y, a0.z, a0.w, a1.x, a1.y, a1.z, a1.w};
            float bl[8] = {b0.x, b0.y, b0.z, b0.w, b1.x, b1.y, b1.z, b1.w};
#pragma unroll
            for (int i = 0; i < 8; i++)
#pragma unroll
                for (int j = 0; j < 8; j++)
                    acc[i][j] = fmaf(a[i], bl[j], acc[i][j]);
        }

        if (more) {
            stx(nxt);
            asm volatile("cp.async.wait_group 0;\n");
        }
        __syncthreads();
    }

    // epilogue
#pragma unroll
    for (int i = 0; i < 8; i++) {
        int gr = rowBase + tr * 8 + i;
        if (gr >= NN) continue;
        float s  = g_dis[gr];
        float s2 = s * s;
        size_t base = (size_t)gr * HC + tc * 8;
#pragma unroll
        for (int j = 0; j < 8; j += 4) {
            float4 v = make_float4(acc[i][j], acc[i][j + 1], acc[i][j + 2], acc[i][j + 3]);
            *reinterpret_cast<float4*>(&g_h[base + j]) = v;
            float4 o = make_float4(v.x * s2, v.y * s2, v.z * s2, v.w * s2);
            *reinterpret_cast<float4*>(&out[base + j]) = o;
        }
    }
}

// ---------------------------------------------------------------------------
// Aggregate: one warp per destination node (CSR gather, no atomics),
// folds bias + PReLU.
// ---------------------------------------------------------------------------
__global__ __launch_bounds__(256)
void k_agg(float* __restrict__ out, const float* __restrict__ b,
           const float* __restrict__ alpha) {
    int node = blockIdx.x * (blockDim.x >> 5) + (threadIdx.x >> 5);
    int lane = threadIdx.x & 31;
    if (node >= NN) return;

    int s = g_off[node];
    int e = g_off[node + 1];

    float4 acc = *reinterpret_cast<const float4*>(&out[(size_t)node * HC + lane * 4]);

    int j = s;
    for (; j + 1 < e; j += 2) {
        int   r0 = g_csr_row[j],     r1 = g_csr_row[j + 1];
        float n0 = g_csr_nrm[j],     n1 = g_csr_nrm[j + 1];
        float4 v0 = *reinterpret_cast<const float4*>(&g_h[(size_t)r0 * HC + lane * 4]);
        float4 v1 = *reinterpret_cast<const float4*>(&g_h[(size_t)r1 * HC + lane * 4]);
        acc.x = fmaf(v0.x, n0, acc.x); acc.y = fmaf(v0.y, n0, acc.y);
        acc.z = fmaf(v0.z, n0, acc.z); acc.w = fmaf(v0.w, n0, acc.w);
        acc.x = fmaf(v1.x, n1, acc.x); acc.y = fmaf(v1.y, n1, acc.y);
        acc.z = fmaf(v1.z, n1, acc.z); acc.w = fmaf(v1.w, n1, acc.w);
    }
    if (j < e) {
        int   r0 = g_csr_row[j];
        float n0 = g_csr_nrm[j];
        float4 v0 = *reinterpret_cast<const float4*>(&g_h[(size_t)r0 * HC + lane * 4]);
        acc.x = fmaf(v0.x, n0, acc.x); acc.y = fmaf(v0.y, n0, acc.y);
        acc.z = fmaf(v0.z, n0, acc.z); acc.w = fmaf(v0.w, n0, acc.w);
    }

    float4 bb = *reinterpret_cast<const float4*>(&b[lane * 4]);
    float4 aa = *reinterpret_cast<const float4*>(&alpha[lane * 4]);
    acc.x += bb.x; acc.y += bb.y; acc.z += bb.z; acc.w += bb.w;
    acc.x = acc.x >= 0.f ? acc.x : aa.x * acc.x;
    acc.y = acc.y >= 0.f ? acc.y : aa.y * acc.y;
    acc.z = acc.z >= 0.f ? acc.z : aa.z * acc.z;
    acc.w = acc.w >= 0.f ? acc.w : aa.w * acc.w;
    *reinterpret_cast<float4*>(&out[(size_t)node * HC + lane * 4]) = acc;
}

// ---------------------------------------------------------------------------
extern "C" void kernel_launch(void* const* d_in, const int* in_sizes, int n_in,
                              void* d_out, int out_size) {
    const float* x  = (const float*)d_in[0];
    const int*   ei = (const int*)d_in[1];     // int32 (JAX x64-disabled downcast)
    const float* ew = (const float*)d_in[2];
    const float* W  = (const float*)d_in[3];
    const float* b  = (const float*)d_in[4];
    const float* al = (const float*)d_in[5];
    float* out = (float*)d_out;

    k_deg_init<<<(NN + 255) / 256, 256>>>();
    k_deg_count<<<(NE + 255) / 256, 256>>>(ei, ew);
    k_scan_blk<<<NBLK, SCAN_B>>>();
    k_scan_top<<<1, 32>>>();
    k_scan_add<<<NBLK, SCAN_B>>>();
    k_fill<<<(NE + 255) / 256, 256>>>(ei, ew);
    k_gemm<<<(NN + BM - 1) / BM, 256>>>(x, W, out);
    k_agg<<<(NN * 32 + 255) / 256, 256>>>(out, b, al);
}

// round 10
// speedup vs baseline: 2.3257x; 1.1487x over previous
#include <cuda_runtime.h>
#include <cuda_bf16.h>
#include <cstdint>

#define NN 50000
#define NE 800000
#define INC 256
#define HC  128

#define NROWS_PAD 50048   // 391 * 128

// Scratch (no cudaMalloc allowed)
__device__ float g_h[(size_t)NN * HC];
__device__ float g_deg[NN];
__device__ float g_dis[NN];
__device__ int   g_cnt[NN];
__device__ int   g_off[NN + 1];
__device__ int   g_cursor[NN];
__device__ int   g_csr_row[NE];
__device__ float g_csr_nrm[NE];
__device__ __nv_bfloat16 g_xs[(size_t)NROWS_PAD * 512];  // [hi(256) | lo(256)] per row
__device__ __nv_bfloat16 g_wcat[768 * 128];              // [Whi; Wlo; Whi]

#define SCAN_B 1024
#define NBLK ((NN + SCAN_B - 1) / SCAN_B)   // 49
__device__ int g_blkoff[64];

// ---------------------------------------------------------------------------
// fp32 -> bf16 hi/lo split of x
// ---------------------------------------------------------------------------
__global__ void k_convert(const float* __restrict__ x) {
    int i = blockIdx.x * blockDim.x + threadIdx.x;   // one float4 each
    if (i >= NN * INC / 4) return;
    int m  = i >> 6;          // 64 float4 per row
    int c4 = i & 63;
    float4 v = *reinterpret_cast<const float4*>(&x[(size_t)m * INC + c4 * 4]);
    __nv_bfloat16 h0 = __float2bfloat16(v.x), h1 = __float2bfloat16(v.y);
    __nv_bfloat16 h2 = __float2bfloat16(v.z), h3 = __float2bfloat16(v.w);
    __nv_bfloat16 l0 = __float2bfloat16(v.x - __bfloat162float(h0));
    __nv_bfloat16 l1 = __float2bfloat16(v.y - __bfloat162float(h1));
    __nv_bfloat16 l2 = __float2bfloat16(v.z - __bfloat162float(h2));
    __nv_bfloat16 l3 = __float2bfloat16(v.w - __bfloat162float(h3));
    uint2 ph, pl;
    ph.x = ((uint32_t)__bfloat16_as_ushort(h1) << 16) | __bfloat16_as_ushort(h0);
    ph.y = ((uint32_t)__bfloat16_as_ushort(h3) << 16) | __bfloat16_as_ushort(h2);
    pl.x = ((uint32_t)__bfloat16_as_ushort(l1) << 16) | __bfloat16_as_ushort(l0);
    pl.y = ((uint32_t)__bfloat16_as_ushort(l3) << 16) | __bfloat16_as_ushort(l2);
    *reinterpret_cast<uint2*>(&g_xs[(size_t)m * 512 + c4 * 4])       = ph;
    *reinterpret_cast<uint2*>(&g_xs[(size_t)m * 512 + 256 + c4 * 4]) = pl;
}

// W -> [Whi(256); Wlo(256); Whi(256)] bf16
__global__ void k_wcat(const float* __restrict__ W) {
    int i = blockIdx.x * blockDim.x + threadIdx.x;
    if (i >= 768 * 128) return;
    int kr = i >> 7, c = i & 127;
    float w = W[(size_t)(kr & 255) * 128 + c];
    __nv_bfloat16 h = __float2bfloat16(w);
    g_wcat[i] = (kr >= 256 && kr < 512) ? __float2bfloat16(w - __bfloat162float(h)) : h;
}

// ---------------------------------------------------------------------------
__global__ void k_deg_init() {
    int i = blockIdx.x * blockDim.x + threadIdx.x;
    if (i < NN) { g_deg[i] = 1.0f; g_cnt[i] = 0; }
}

__global__ void k_deg_count(const int* __restrict__ ei,
                            const float* __restrict__ ew) {
    int e = blockIdx.x * blockDim.x + threadIdx.x;
    if (e < NE) {
        int c = ei[NE + e];
        atomicAdd(&g_deg[c], ew[e]);
        atomicAdd(&g_cnt[c], 1);
    }
}

// ---------------------------------------------------------------------------
// Scan phase 1: per-block exclusive scan of g_cnt + block totals (+ g_dis)
// ---------------------------------------------------------------------------
__global__ void k_scan_blk() {
    __shared__ int warpsum[32];
    int tid = threadIdx.x, lane = tid & 31, wid = tid >> 5;
    int i = blockIdx.x * SCAN_B + tid;

    if (i < NN) {
        float d = g_deg[i];
        g_dis[i] = d > 0.0f ? rsqrtf(d) : 0.0f;
    }

    int v = (i < NN) ? g_cnt[i] : 0;
    int x = v;
#pragma unroll
    for (int o = 1; o < 32; o <<= 1) {
        int t = __shfl_up_sync(0xFFFFFFFFu, x, o);
        if (lane >= o) x += t;
    }
    if (lane == 31) warpsum[wid] = x;
    __syncthreads();
    if (wid == 0) {
        int w = warpsum[lane];
#pragma unroll
        for (int o = 1; o < 32; o <<= 1) {
            int t = __shfl_up_sync(0xFFFFFFFFu, w, o);
            if (lane >= o) w += t;
        }
        warpsum[lane] = w;
    }
    __syncthreads();
    int pre = (wid > 0) ? warpsum[wid - 1] : 0;
    if (i < NN) g_off[i] = pre + x - v;
    if (tid == 0) g_blkoff[blockIdx.x] = warpsum[31];
}

__global__ void k_scan_top() {
    int lane = threadIdx.x;   // 32 threads
    int v0 = (lane < NBLK) ? g_blkoff[lane] : 0;
    int v1 = (lane + 32 < NBLK) ? g_blkoff[lane + 32] : 0;
    int x0 = v0;
#pragma unroll
    for (int o = 1; o < 32; o <<= 1) {
        int t = __shfl_up_sync(0xFFFFFFFFu, x0, o);
        if (lane >= o) x0 += t;
    }
    int tot0 = __shfl_sync(0xFFFFFFFFu, x0, 31);
    int x1 = v1;
#pragma unroll
    for (int o = 1; o < 32; o <<= 1) {
        int t = __shfl_up_sync(0xFFFFFFFFu, x1, o);
        if (lane >= o) x1 += t;
    }
    g_blkoff[lane]      = x0 - v0;
    g_blkoff[lane + 32] = tot0 + x1 - v1;
    if (lane == 31) g_off[NN] = tot0 + __shfl_sync(0xFFFFFFFFu, x1, 31);
}

__global__ void k_scan_add() {
    int i = blockIdx.x * SCAN_B + threadIdx.x;
    if (i < NN) {
        int o = g_off[i] + g_blkoff[blockIdx.x];
        g_off[i] = o;
        g_cursor[i] = o;
    }
}

// ---------------------------------------------------------------------------
__global__ void k_fill(const int* __restrict__ ei,
                       const float* __restrict__ ew) {
    int e = blockIdx.x * blockDim.x + threadIdx.x;
    if (e < NE) {
        int r = ei[e];
        int c = ei[NE + e];
        int pos = atomicAdd(&g_cursor[c], 1);
        g_csr_row[pos] = r;
        g_csr_nrm[pos] = g_dis[r] * ew[e] * g_dis[c];
    }
}

// ---------------------------------------------------------------------------
// Tensor GEMM: h = A'[NROWS x 768] * B'[768 x 128], bf16 mma.sync, fp32 acc
//   A' cols: [0,512): xhi (xs col k&255);  [512,768): xlo (xs col k-256)
//   B' = g_wcat. Epilogue: g_h + self-loop out = h * dis^2
// ---------------------------------------------------------------------------
#define GM 128
#define GK 32
#define KTOT 768
#define NKT (KTOT / GK)     // 24
#define ASTR 40             // bf16 units (80B row stride: ldmatrix conflict-free)
#define BSTR 136            // (272B row stride)

__device__ __forceinline__ void cp16(void* s, const void* g) {
    uint32_t sa = (uint32_t)__cvta_generic_to_shared(s);
    asm volatile("cp.async.cg.shared.global [%0], [%1], 16;\n" :: "r"(sa), "l"(g));
}
__device__ __forceinline__ void ldm_x4(uint32_t* r, uint32_t a) {
    asm volatile("ldmatrix.sync.aligned.m8n8.x4.shared.b16 {%0,%1,%2,%3}, [%4];"
                 : "=r"(r[0]), "=r"(r[1]), "=r"(r[2]), "=r"(r[3]) : "r"(a));
}
__device__ __forceinline__ void ldm_x4t(uint32_t* r, uint32_t a) {
    asm volatile("ldmatrix.sync.aligned.m8n8.x4.trans.shared.b16 {%0,%1,%2,%3}, [%4];"
                 : "=r"(r[0]), "=r"(r[1]), "=r"(r[2]), "=r"(r[3]) : "r"(a));
}
__device__ __forceinline__ void mma16816(float* c, const uint32_t* a, const uint32_t* b) {
    asm volatile("mma.sync.aligned.m16n8k16.row.col.f32.bf16.bf16.f32 "
                 "{%0,%1,%2,%3}, {%4,%5,%6,%7}, {%8,%9}, {%0,%1,%2,%3};"
                 : "+f"(c[0]), "+f"(c[1]), "+f"(c[2]), "+f"(c[3])
                 : "r"(a[0]), "r"(a[1]), "r"(a[2]), "r"(a[3]), "r"(b[0]), "r"(b[1]));
}

__global__ __launch_bounds__(256, 2)
void k_gemm_mma(float* __restrict__ out) {
    __shared__ __nv_bfloat16 As[2][GM * ASTR];   // 10240 B each
    __shared__ __nv_bfloat16 Bs[2][GK * BSTR];   // 8704 B each

    int tid = threadIdx.x;
    int wid = tid >> 5, lane = tid & 31;
    int wm = wid >> 1, wn = wid & 1;             // 4x2 warps: 32 rows x 64 cols each
    int rowBase = blockIdx.x * GM;

    float acc[2][8][4];
#pragma unroll
    for (int i = 0; i < 2; i++)
#pragma unroll
        for (int j = 0; j < 8; j++)
#pragma unroll
            for (int q = 0; q < 4; q++) acc[i][j][q] = 0.0f;

    auto lda = [&](int t, int buf) {
        int kk = t * GK;
        int acol = (kk < 512) ? (kk & 255) : (kk - 256);
#pragma unroll
        for (int l = 0; l < 2; l++) {
            int idx = tid + l * 256;      // 0..511
            int r  = idx >> 2;            // 128 rows
            int cq = idx & 3;             // 4 chunks of 8 bf16
            cp16(&As[buf][r * ASTR + cq * 8],
                 &g_xs[(size_t)(rowBase + r) * 512 + acol + cq * 8]);
        }
    };
    auto ldb = [&](int t, int buf) {
        int kk = t * GK;
#pragma unroll
        for (int l = 0; l < 2; l++) {
            int idx = tid + l * 256;      // 0..511
            int kr = idx >> 4;            // 32 rows
            int cq = idx & 15;            // 16 chunks of 8 bf16
            cp16(&Bs[buf][kr * BSTR + cq * 8],
                 &g_wcat[(size_t)(kk + kr) * 128 + cq * 8]);
        }
    };

    lda(0, 0); ldb(0, 0);
    asm volatile("cp.async.commit_group;\n");
    asm volatile("cp.async.wait_group 0;\n");
    __syncthreads();

    for (int t = 0; t < NKT; t++) {
        int cur = t & 1, nxt = cur ^ 1;
        bool more = (t + 1 < NKT);
        if (more) {
            lda(t + 1, nxt); ldb(t + 1, nxt);
            asm volatile("cp.async.commit_group;\n");
        }

        uint32_t abase = (uint32_t)__cvta_generic_to_shared(&As[cur][0]);
        uint32_t bbase = (uint32_t)__cvta_generic_to_shared(&Bs[cur][0]);
        int lr = lane & 15, lc = (lane >> 4) * 8;

#pragma unroll
        for (int ks = 0; ks < 2; ks++) {
            int kb = ks * 16;
            uint32_t af[2][4], bf[4][4];
#pragma unroll
            for (int mt = 0; mt < 2; mt++) {
                int R = wm * 32 + mt * 16;
                ldm_x4(af[mt], abase + ((R + lr) * ASTR + kb + lc) * 2);
            }
#pragma unroll
            for (int nt = 0; nt < 4; nt++) {
                int nb = wn * 64 + nt * 16;
                ldm_x4t(bf[nt], bbase + ((kb + lr) * BSTR + nb + lc) * 2);
            }
#pragma unroll
            for (int mt = 0; mt < 2; mt++)
#pragma unroll
                for (int n8 = 0; n8 < 8; n8++)
                    mma16816(acc[mt][n8], af[mt], &bf[n8 >> 1][(n8 & 1) * 2]);
        }

        if (more) asm volatile("cp.async.wait_group 0;\n");
        __syncthreads();
    }

    // Epilogue: c0,c1 -> (row, col..col+1); c2,c3 -> (row+8, col..col+1)
    int r = lane >> 2, cq = lane & 3;
#pragma unroll
    for (int mt = 0; mt < 2; mt++) {
        int row0 = rowBase + wm * 32 + mt * 16 + r;
        int row1 = row0 + 8;
        float s0 = 0.f, s1 = 0.f;
        if (row0 < NN) { float s = g_dis[row0]; s0 = s * s; }
        if (row1 < NN) { float s = g_dis[row1]; s1 = s * s; }
#pragma unroll
        for (int n8 = 0; n8 < 8; n8++) {
            int col = wn * 64 + n8 * 8 + cq * 2;
            if (row0 < NN) {
                float2 v = make_float2(acc[mt][n8][0], acc[mt][n8][1]);
                *reinterpret_cast<float2*>(&g_h[(size_t)row0 * HC + col]) = v;
                *reinterpret_cast<float2*>(&out[(size_t)row0 * HC + col]) =
                    make_float2(v.x * s0, v.y * s0);
            }
            if (row1 < NN) {
                float2 v = make_float2(acc[mt][n8][2], acc[mt][n8][3]);
                *reinterpret_cast<float2*>(&g_h[(size_t)row1 * HC + col]) = v;
                *reinterpret_cast<float2*>(&out[(size_t)row1 * HC + col]) =
                    make_float2(v.x * s1, v.y * s1);
            }
        }
    }
}

// ---------------------------------------------------------------------------
// Aggregate: one warp per destination node (CSR gather, no atomics),
// folds bias + PReLU.
// ---------------------------------------------------------------------------
__global__ __launch_bounds__(256)
void k_agg(float* __restrict__ out, const float* __restrict__ b,
           const float* __restrict__ alpha) {
    int node = blockIdx.x * (blockDim.x >> 5) + (threadIdx.x >> 5);
    int lane = threadIdx.x & 31;
    if (node >= NN) return;

    int s = g_off[node];
    int e = g_off[node + 1];

    float4 acc = *reinterpret_cast<const float4*>(&out[(size_t)node * HC + lane * 4]);

    int j = s;
    for (; j + 1 < e; j += 2) {
        int   r0 = g_csr_row[j],     r1 = g_csr_row[j + 1];
        float n0 = g_csr_nrm[j],     n1 = g_csr_nrm[j + 1];
        float4 v0 = *reinterpret_cast<const float4*>(&g_h[(size_t)r0 * HC + lane * 4]);
        float4 v1 = *reinterpret_cast<const float4*>(&g_h[(size_t)r1 * HC + lane * 4]);
        acc.x = fmaf(v0.x, n0, acc.x); acc.y = fmaf(v0.y, n0, acc.y);
        acc.z = fmaf(v0.z, n0, acc.z); acc.w = fmaf(v0.w, n0, acc.w);
        acc.x = fmaf(v1.x, n1, acc.x); acc.y = fmaf(v1.y, n1, acc.y);
        acc.z = fmaf(v1.z, n1, acc.z); acc.w = fmaf(v1.w, n1, acc.w);
    }
    if (j < e) {
        int   r0 = g_csr_row[j];
        float n0 = g_csr_nrm[j];
        float4 v0 = *reinterpret_cast<const float4*>(&g_h[(size_t)r0 * HC + lane * 4]);
        acc.x = fmaf(v0.x, n0, acc.x); acc.y = fmaf(v0.y, n0, acc.y);
        acc.z = fmaf(v0.z, n0, acc.z); acc.w = fmaf(v0.w, n0, acc.w);
    }

    float4 bb = *reinterpret_cast<const float4*>(&b[lane * 4]);
    float4 aa = *reinterpret_cast<const float4*>(&alpha[lane * 4]);
    acc.x += bb.x; acc.y += bb.y; acc.z += bb.z; acc.w += bb.w;
    acc.x = acc.x >= 0.f ? acc.x : aa.x * acc.x;
    acc.y = acc.y >= 0.f ? acc.y : aa.y * acc.y;
    acc.z = acc.z >= 0.f ? acc.z : aa.z * acc.z;
    acc.w = acc.w >= 0.f ? acc.w : aa.w * acc.w;
    *reinterpret_cast<float4*>(&out[(size_t)node * HC + lane * 4]) = acc;
}

// ---------------------------------------------------------------------------
extern "C" void kernel_launch(void* const* d_in, const int* in_sizes, int n_in,
                              void* d_out, int out_size) {
    const float* x  = (const float*)d_in[0];
    const int*   ei = (const int*)d_in[1];     // int32 (JAX x64-disabled downcast)
    const float* ew = (const float*)d_in[2];
    const float* W  = (const float*)d_in[3];
    const float* b  = (const float*)d_in[4];
    const float* al = (const float*)d_in[5];
    float* out = (float*)d_out;

    k_convert<<<(NN * INC / 4 + 255) / 256, 256>>>(x);
    k_wcat<<<(768 * 128 + 255) / 256, 256>>>(W);
    k_deg_init<<<(NN + 255) / 256, 256>>>();
    k_deg_count<<<(NE + 255) / 256, 256>>>(ei, ew);
    k_scan_blk<<<NBLK, SCAN_B>>>();
    k_scan_top<<<1, 32>>>();
    k_scan_add<<<NBLK, SCAN_B>>>();
    k_fill<<<(NE + 255) / 256, 256>>>(ei, ew);
    k_gemm_mma<<<NROWS_PAD / GM, 256>>>(out);
    k_agg<<<(NN * 32 + 255) / 256, 256>>>(out, b, al);
}

// round 11
// speedup vs baseline: 2.3958x; 1.0301x over previous
#include <cuda_runtime.h>
#include <cuda_bf16.h>
#include <cstdint>

#define NN 50000
#define NE 800000
#define INC 256
#define HC  128

#define NROWS_PAD 50048   // 391 * 128

// Scratch (no cudaMalloc allowed)
__device__ float g_h[(size_t)NN * HC];
__device__ float g_dis[NN];
__device__ int   g_cnt[NN];
__device__ int   g_off[NN + 1];
__device__ int   g_cursor[NN];
__device__ int2  g_csr[NE];              // {row | col<<16, ew_bits -> nrm_bits}
__device__ __nv_bfloat16 g_wcat[768 * 128];   // [Whi; Wlo; Whi]

#define SCAN_B 1024
#define NBLK ((NN + SCAN_B - 1) / SCAN_B)   // 49
__device__ int g_blkoff[64];

// ---------------------------------------------------------------------------
// W -> [Whi(256); Wlo(256); Whi(256)] bf16
// ---------------------------------------------------------------------------
__global__ void k_wcat(const float* __restrict__ W) {
    int i = blockIdx.x * blockDim.x + threadIdx.x;
    if (i >= 768 * 128) return;
    int kr = i >> 7, c = i & 127;
    float w = W[(size_t)(kr & 255) * 128 + c];
    __nv_bfloat16 h = __float2bfloat16(w);
    g_wcat[i] = (kr >= 256 && kr < 512) ? __float2bfloat16(w - __bfloat162float(h)) : h;
}

// ---------------------------------------------------------------------------
__global__ void k_cnt_init() {
    int i = blockIdx.x * blockDim.x + threadIdx.x;
    if (i < NN) g_cnt[i] = 0;
}

__global__ void k_count(const int* __restrict__ ei) {
    int e = blockIdx.x * blockDim.x + threadIdx.x;
    if (e < NE) atomicAdd(&g_cnt[ei[NE + e]], 1);
}

// ---------------------------------------------------------------------------
// Scan phases (exclusive prefix sum of g_cnt -> g_off)
// ---------------------------------------------------------------------------
__global__ void k_scan_blk() {
    __shared__ int warpsum[32];
    int tid = threadIdx.x, lane = tid & 31, wid = tid >> 5;
    int i = blockIdx.x * SCAN_B + tid;

    int v = (i < NN) ? g_cnt[i] : 0;
    int x = v;
#pragma unroll
    for (int o = 1; o < 32; o <<= 1) {
        int t = __shfl_up_sync(0xFFFFFFFFu, x, o);
        if (lane >= o) x += t;
    }
    if (lane == 31) warpsum[wid] = x;
    __syncthreads();
    if (wid == 0) {
        int w = warpsum[lane];
#pragma unroll
        for (int o = 1; o < 32; o <<= 1) {
            int t = __shfl_up_sync(0xFFFFFFFFu, w, o);
            if (lane >= o) w += t;
        }
        warpsum[lane] = w;
    }
    __syncthreads();
    int pre = (wid > 0) ? warpsum[wid - 1] : 0;
    if (i < NN) g_off[i] = pre + x - v;
    if (tid == 0) g_blkoff[blockIdx.x] = warpsum[31];
}

__global__ void k_scan_top() {
    int lane = threadIdx.x;   // 32 threads
    int v0 = (lane < NBLK) ? g_blkoff[lane] : 0;
    int v1 = (lane + 32 < NBLK) ? g_blkoff[lane + 32] : 0;
    int x0 = v0;
#pragma unroll
    for (int o = 1; o < 32; o <<= 1) {
        int t = __shfl_up_sync(0xFFFFFFFFu, x0, o);
        if (lane >= o) x0 += t;
    }
    int tot0 = __shfl_sync(0xFFFFFFFFu, x0, 31);
    int x1 = v1;
#pragma unroll
    for (int o = 1; o < 32; o <<= 1) {
        int t = __shfl_up_sync(0xFFFFFFFFu, x1, o);
        if (lane >= o) x1 += t;
    }
    g_blkoff[lane]      = x0 - v0;
    g_blkoff[lane + 32] = tot0 + x1 - v1;
    if (lane == 31) g_off[NN] = tot0 + __shfl_sync(0xFFFFFFFFu, x1, 31);
}

__global__ void k_scan_add() {
    int i = blockIdx.x * SCAN_B + threadIdx.x;
    if (i < NN) {
        int o = g_off[i] + g_blkoff[blockIdx.x];
        g_off[i] = o;
        g_cursor[i] = o;
    }
}

// ---------------------------------------------------------------------------
// Fill CSR buckets: packed {row | col<<16, ew}
// ---------------------------------------------------------------------------
__global__ void k_fill(const int* __restrict__ ei,
                       const float* __restrict__ ew) {
    int e = blockIdx.x * blockDim.x + threadIdx.x;
    if (e < NE) {
        int r = ei[e];
        int c = ei[NE + e];
        int pos = atomicAdd(&g_cursor[c], 1);
        g_csr[pos] = make_int2(r | (c << 16), __float_as_int(ew[e]));
    }
}

// Per-node degree + dis (deg = 1 + sum of bucket weights; always >= 1)
__global__ __launch_bounds__(256)
void k_degdis() {
    int node = blockIdx.x * (blockDim.x >> 5) + (threadIdx.x >> 5);
    int lane = threadIdx.x & 31;
    if (node >= NN) return;
    int s = g_off[node], e = g_off[node + 1];
    float sum = 0.0f;
    for (int j = s + lane; j < e; j += 32)
        sum += __int_as_float(g_csr[j].y);
#pragma unroll
    for (int o = 16; o > 0; o >>= 1)
        sum += __shfl_xor_sync(0xFFFFFFFFu, sum, o);
    if (lane == 0) g_dis[node] = rsqrtf(1.0f + sum);
}

// Edge-parallel norm: overwrite ew slot with dis[r]*ew*dis[c]
__global__ void k_nrm() {
    int j = blockIdx.x * blockDim.x + threadIdx.x;
    if (j >= NE) return;
    int2 ent = g_csr[j];
    int r = ent.x & 0xFFFF;
    int c = (ent.x >> 16) & 0xFFFF;
    float nrm = g_dis[r] * __int_as_float(ent.y) * g_dis[c];
    g_csr[j].y = __float_as_int(nrm);
}

// ---------------------------------------------------------------------------
// Tensor GEMM with fused fp32->bf16 hi/lo split of x.
//   Logical: h = A'[N x 768] * B'[768 x 128]; A' = [xhi|xhi|xlo], B' = g_wcat
//   A tiles loaded fp32 from x, converted in registers, stored bf16 to smem.
//   Epilogue writes g_h only (self-loop handled in k_agg).
// ---------------------------------------------------------------------------
#define GM 128
#define GK 32
#define NKT 24
#define ASTR 40             // bf16 units (80B row stride: ldmatrix conflict-free)
#define BSTR 136            // (272B row stride)

__device__ __forceinline__ void cp16(void* s, const void* g) {
    uint32_t sa = (uint32_t)__cvta_generic_to_shared(s);
    asm volatile("cp.async.cg.shared.global [%0], [%1], 16;\n" :: "r"(sa), "l"(g));
}
__device__ __forceinline__ void ldm_x4(uint32_t* r, uint32_t a) {
    asm volatile("ldmatrix.sync.aligned.m8n8.x4.shared.b16 {%0,%1,%2,%3}, [%4];"
                 : "=r"(r[0]), "=r"(r[1]), "=r"(r[2]), "=r"(r[3]) : "r"(a));
}
__device__ __forceinline__ void ldm_x4t(uint32_t* r, uint32_t a) {
    asm volatile("ldmatrix.sync.aligned.m8n8.x4.trans.shared.b16 {%0,%1,%2,%3}, [%4];"
                 : "=r"(r[0]), "=r"(r[1]), "=r"(r[2]), "=r"(r[3]) : "r"(a));
}
__device__ __forceinline__ void mma16816(float* c, const uint32_t* a, const uint32_t* b) {
    asm volatile("mma.sync.aligned.m16n8k16.row.col.f32.bf16.bf16.f32 "
                 "{%0,%1,%2,%3}, {%4,%5,%6,%7}, {%8,%9}, {%0,%1,%2,%3};"
                 : "+f"(c[0]), "+f"(c[1]), "+f"(c[2]), "+f"(c[3])
                 : "r"(a[0]), "r"(a[1]), "r"(a[2]), "r"(a[3]), "r"(b[0]), "r"(b[1]));
}

__device__ __forceinline__ uint2 pack_hi(float4 v) {
    __nv_bfloat16 h0 = __float2bfloat16(v.x), h1 = __float2bfloat16(v.y);
    __nv_bfloat16 h2 = __float2bfloat16(v.z), h3 = __float2bfloat16(v.w);
    uint2 p;
    p.x = ((uint32_t)__bfloat16_as_ushort(h1) << 16) | __bfloat16_as_ushort(h0);
    p.y = ((uint32_t)__bfloat16_as_ushort(h3) << 16) | __bfloat16_as_ushort(h2);
    return p;
}
__device__ __forceinline__ uint2 pack_lo(float4 v) {
    __nv_bfloat16 h0 = __float2bfloat16(v.x), h1 = __float2bfloat16(v.y);
    __nv_bfloat16 h2 = __float2bfloat16(v.z), h3 = __float2bfloat16(v.w);
    __nv_bfloat16 l0 = __float2bfloat16(v.x - __bfloat162float(h0));
    __nv_bfloat16 l1 = __float2bfloat16(v.y - __bfloat162float(h1));
    __nv_bfloat16 l2 = __float2bfloat16(v.z - __bfloat162float(h2));
    __nv_bfloat16 l3 = __float2bfloat16(v.w - __bfloat162float(h3));
    uint2 p;
    p.x = ((uint32_t)__bfloat16_as_ushort(l1) << 16) | __bfloat16_as_ushort(l0);
    p.y = ((uint32_t)__bfloat16_as_ushort(l3) << 16) | __bfloat16_as_ushort(l2);
    return p;
}

__global__ __launch_bounds__(256, 2)
void k_gemm_mma(const float* __restrict__ x) {
    __shared__ __nv_bfloat16 As[2][GM * ASTR];   // 10240 B each
    __shared__ __nv_bfloat16 Bs[2][GK * BSTR];   // 8704 B each

    int tid = threadIdx.x;
    int wid = tid >> 5, lane = tid & 31;
    int wm = wid >> 1, wn = wid & 1;             // 4x2 warps: 32 rows x 64 cols
    int rowBase = blockIdx.x * GM;

    float acc[2][8][4];
#pragma unroll
    for (int i = 0; i < 2; i++)
#pragma unroll
        for (int j = 0; j < 8; j++)
#pragma unroll
            for (int q = 0; q < 4; q++) acc[i][j][q] = 0.0f;

    float4 xstage[4];

    // A: tile t -> x cols (t<16 ? (t&7)*32 : (t-16)*32), hi for t<16, lo after
    auto ldx = [&](int t) {
        int xcol = (t < 16 ? (t & 7) : (t - 16)) * GK;
#pragma unroll
        for (int l = 0; l < 4; l++) {
            int idx = tid + l * 256;      // 0..1023
            int r  = idx >> 3;            // 128 rows
            int c8 = idx & 7;             // 8 float4 per row
            int gr = rowBase + r;
            float4 v = make_float4(0.f, 0.f, 0.f, 0.f);
            if (gr < NN)
                v = *reinterpret_cast<const float4*>(&x[(size_t)gr * INC + xcol + c8 * 4]);
            xstage[l] = v;
        }
    };
    auto stx = [&](int t, int buf) {
        bool lo = (t >= 16);
#pragma unroll
        for (int l = 0; l < 4; l++) {
            int idx = tid + l * 256;
            int r  = idx >> 3;
            int c8 = idx & 7;
            uint2 p = lo ? pack_lo(xstage[l]) : pack_hi(xstage[l]);
            *reinterpret_cast<uint2*>(&As[buf][r * ASTR + c8 * 4]) = p;
        }
    };
    auto ldb = [&](int t, int buf) {
#pragma unroll
        for (int l = 0; l < 2; l++) {
            int idx = tid + l * 256;
            int kr = idx >> 4;            // 32 rows
            int cq = idx & 15;            // 16 chunks of 8 bf16
            cp16(&Bs[buf][kr * BSTR + cq * 8],
                 &g_wcat[(size_t)(t * GK + kr) * 128 + cq * 8]);
        }
        asm volatile("cp.async.commit_group;\n");
    };

    ldx(0); ldb(0, 0); stx(0, 0);
    asm volatile("cp.async.wait_group 0;\n");
    __syncthreads();

    for (int t = 0; t < NKT; t++) {
        int cur = t & 1, nxt = cur ^ 1;
        bool more = (t + 1 < NKT);
        if (more) { ldx(t + 1); ldb(t + 1, nxt); }

        uint32_t abase = (uint32_t)__cvta_generic_to_shared(&As[cur][0]);
        uint32_t bbase = (uint32_t)__cvta_generic_to_shared(&Bs[cur][0]);
        int lr = lane & 15, lc = (lane >> 4) * 8;

#pragma unroll
        for (int ks = 0; ks < 2; ks++) {
            int kb = ks * 16;
            uint32_t af[2][4], bf[4][4];
#pragma unroll
            for (int mt = 0; mt < 2; mt++) {
                int R = wm * 32 + mt * 16;
                ldm_x4(af[mt], abase + ((R + lr) * ASTR + kb + lc) * 2);
            }
#pragma unroll
            for (int nt = 0; nt < 4; nt++) {
                int nb = wn * 64 + nt * 16;
                ldm_x4t(bf[nt], bbase + ((kb + lr) * BSTR + nb + lc) * 2);
            }
#pragma unroll
            for (int mt = 0; mt < 2; mt++)
#pragma unroll
                for (int n8 = 0; n8 < 8; n8++)
                    mma16816(acc[mt][n8], af[mt], &bf[n8 >> 1][(n8 & 1) * 2]);
        }

        if (more) {
            stx(t + 1, nxt);
            asm volatile("cp.async.wait_group 0;\n");
        }
        __syncthreads();
    }

    // Epilogue: write g_h only
    int r = lane >> 2, cq = lane & 3;
#pragma unroll
    for (int mt = 0; mt < 2; mt++) {
        int row0 = rowBase + wm * 32 + mt * 16 + r;
        int row1 = row0 + 8;
#pragma unroll
        for (int n8 = 0; n8 < 8; n8++) {
            int col = wn * 64 + n8 * 8 + cq * 2;
            if (row0 < NN)
                *reinterpret_cast<float2*>(&g_h[(size_t)row0 * HC + col]) =
                    make_float2(acc[mt][n8][0], acc[mt][n8][1]);
            if (row1 < NN)
                *reinterpret_cast<float2*>(&g_h[(size_t)row1 * HC + col]) =
                    make_float2(acc[mt][n8][2], acc[mt][n8][3]);
        }
    }
}

// ---------------------------------------------------------------------------
// Aggregate: warp per destination node. Self-loop + CSR gather + bias + PReLU.
// ---------------------------------------------------------------------------
__global__ __launch_bounds__(256)
void k_agg(float* __restrict__ out, const float* __restrict__ b,
           const float* __restrict__ alpha) {
    int node = blockIdx.x * (blockDim.x >> 5) + (threadIdx.x >> 5);
    int lane = threadIdx.x & 31;
    if (node >= NN) return;

    int s = g_off[node];
    int e = g_off[node + 1];

    float ds = g_dis[node];
    float s2 = ds * ds;
    float4 own = *reinterpret_cast<const float4*>(&g_h[(size_t)node * HC + lane * 4]);
    float4 bb  = *reinterpret_cast<const float4*>(&b[lane * 4]);
    float4 acc = make_float4(fmaf(own.x, s2, bb.x), fmaf(own.y, s2, bb.y),
                             fmaf(own.z, s2, bb.z), fmaf(own.w, s2, bb.w));

    int j = s;
    for (; j + 1 < e; j += 2) {
        int2 e0 = g_csr[j];
        int2 e1 = g_csr[j + 1];
        int   r0 = e0.x & 0xFFFF,          r1 = e1.x & 0xFFFF;
        float n0 = __int_as_float(e0.y),   n1 = __int_as_float(e1.y);
        float4 v0 = *reinterpret_cast<const float4*>(&g_h[(size_t)r0 * HC + lane * 4]);
        float4 v1 = *reinterpret_cast<const float4*>(&g_h[(size_t)r1 * HC + lane * 4]);
        acc.x = fmaf(v0.x, n0, acc.x); acc.y = fmaf(v0.y, n0, acc.y);
        acc.z = fmaf(v0.z, n0, acc.z); acc.w = fmaf(v0.w, n0, acc.w);
        acc.x = fmaf(v1.x, n1, acc.x); acc.y = fmaf(v1.y, n1, acc.y);
        acc.z = fmaf(v1.z, n1, acc.z); acc.w = fmaf(v1.w, n1, acc.w);
    }
    if (j < e) {
        int2 e0 = g_csr[j];
        int   r0 = e0.x & 0xFFFF;
        float n0 = __int_as_float(e0.y);
        float4 v0 = *reinterpret_cast<const float4*>(&g_h[(size_t)r0 * HC + lane * 4]);
        acc.x = fmaf(v0.x, n0, acc.x); acc.y = fmaf(v0.y, n0, acc.y);
        acc.z = fmaf(v0.z, n0, acc.z); acc.w = fmaf(v0.w, n0, acc.w);
    }

    float4 aa = *reinterpret_cast<const float4*>(&alpha[lane * 4]);
    acc.x = acc.x >= 0.f ? acc.x : aa.x * acc.x;
    acc.y = acc.y >= 0.f ? acc.y : aa.y * acc.y;
    acc.z = acc.z >= 0.f ? acc.z : aa.z * acc.z;
    acc.w = acc.w >= 0.f ? acc.w : aa.w * acc.w;
    *reinterpret_cast<float4*>(&out[(size_t)node * HC + lane * 4]) = acc;
}

// ---------------------------------------------------------------------------
extern "C" void kernel_launch(void* const* d_in, const int* in_sizes, int n_in,
                              void* d_out, int out_size) {
    const float* x  = (const float*)d_in[0];
    const int*   ei = (const int*)d_in[1];     // int32 (JAX x64-disabled downcast)
    const float* ew = (const float*)d_in[2];
    const float* W  = (const float*)d_in[3];
    const float* b  = (const float*)d_in[4];
    const float* al = (const float*)d_in[5];
    float* out = (float*)d_out;

    k_wcat<<<(768 * 128 + 255) / 256, 256>>>(W);
    k_cnt_init<<<(NN + 255) / 256, 256>>>();
    k_count<<<(NE + 255) / 256, 256>>>(ei);
    k_scan_blk<<<NBLK, SCAN_B>>>();
    k_scan_top<<<1, 32>>>();
    k_scan_add<<<NBLK, SCAN_B>>>();
    k_fill<<<(NE + 255) / 256, 256>>>(ei, ew);
    k_degdis<<<(NN * 32 + 255) / 256, 256>>>();
    k_nrm<<<(NE + 255) / 256, 256>>>();
    k_gemm_mma<<<NROWS_PAD / GM, 256>>>(x);
    k_agg<<<(NN * 32 + 255) / 256, 256>>>(out, b, al);
}

// round 12
// speedup vs baseline: 2.7380x; 1.1428x over previous
#include <cuda_runtime.h>
#include <cuda_bf16.h>
#include <cstdint>

#define NN 50000
#define NE 800000
#define INC 256
#define HC  128

#define NROWS_PAD 50048   // 391 * 128

// Scratch (no cudaMalloc allowed)
__device__ float g_h[(size_t)NN * HC];
__device__ float g_dis[NN];
__device__ int   g_cnt[NN];
__device__ int   g_off[NN + 1];
__device__ int   g_cursor[NN];
__device__ int2  g_csr[NE];                   // {row | col<<16, ew_bits}
__device__ __nv_bfloat16 g_wcat[512 * 128];   // [Whi(256); Wlo(256)]

#define SCAN_B 1024
#define NBLK ((NN + SCAN_B - 1) / SCAN_B)   // 49
__device__ int g_blkoff[64];

// ---------------------------------------------------------------------------
// W -> [Whi(256); Wlo(256)] bf16
// ---------------------------------------------------------------------------
__global__ void k_wcat(const float* __restrict__ W) {
    int i = blockIdx.x * blockDim.x + threadIdx.x;
    if (i >= 512 * 128) return;
    int kr = i >> 7, c = i & 127;
    float w = W[(size_t)(kr & 255) * 128 + c];
    __nv_bfloat16 h = __float2bfloat16(w);
    g_wcat[i] = (kr >= 256) ? __float2bfloat16(w - __bfloat162float(h)) : h;
}

// ---------------------------------------------------------------------------
__global__ void k_cnt_init() {
    int i = blockIdx.x * blockDim.x + threadIdx.x;
    if (i < NN) g_cnt[i] = 0;
}

__global__ void k_count(const int* __restrict__ ei) {
    int e = blockIdx.x * blockDim.x + threadIdx.x;
    if (e < NE) atomicAdd(&g_cnt[ei[NE + e]], 1);
}

// ---------------------------------------------------------------------------
// Scan phases (exclusive prefix sum of g_cnt -> g_off)
// ---------------------------------------------------------------------------
__global__ void k_scan_blk() {
    __shared__ int warpsum[32];
    int tid = threadIdx.x, lane = tid & 31, wid = tid >> 5;
    int i = blockIdx.x * SCAN_B + tid;

    int v = (i < NN) ? g_cnt[i] : 0;
    int x = v;
#pragma unroll
    for (int o = 1; o < 32; o <<= 1) {
        int t = __shfl_up_sync(0xFFFFFFFFu, x, o);
        if (lane >= o) x += t;
    }
    if (lane == 31) warpsum[wid] = x;
    __syncthreads();
    if (wid == 0) {
        int w = warpsum[lane];
#pragma unroll
        for (int o = 1; o < 32; o <<= 1) {
            int t = __shfl_up_sync(0xFFFFFFFFu, w, o);
            if (lane >= o) w += t;
        }
        warpsum[lane] = w;
    }
    __syncthreads();
    int pre = (wid > 0) ? warpsum[wid - 1] : 0;
    if (i < NN) g_off[i] = pre + x - v;
    if (tid == 0) g_blkoff[blockIdx.x] = warpsum[31];
}

__global__ void k_scan_top() {
    int lane = threadIdx.x;   // 32 threads
    int v0 = (lane < NBLK) ? g_blkoff[lane] : 0;
    int v1 = (lane + 32 < NBLK) ? g_blkoff[lane + 32] : 0;
    int x0 = v0;
#pragma unroll
    for (int o = 1; o < 32; o <<= 1) {
        int t = __shfl_up_sync(0xFFFFFFFFu, x0, o);
        if (lane >= o) x0 += t;
    }
    int tot0 = __shfl_sync(0xFFFFFFFFu, x0, 31);
    int x1 = v1;
#pragma unroll
    for (int o = 1; o < 32; o <<= 1) {
        int t = __shfl_up_sync(0xFFFFFFFFu, x1, o);
        if (lane >= o) x1 += t;
    }
    g_blkoff[lane]      = x0 - v0;
    g_blkoff[lane + 32] = tot0 + x1 - v1;
    if (lane == 31) g_off[NN] = tot0 + __shfl_sync(0xFFFFFFFFu, x1, 31);
}

__global__ void k_scan_add() {
    int i = blockIdx.x * SCAN_B + threadIdx.x;
    if (i < NN) {
        int o = g_off[i] + g_blkoff[blockIdx.x];
        g_off[i] = o;
        g_cursor[i] = o;
    }
}

// ---------------------------------------------------------------------------
// Fill CSR buckets: packed {row | col<<16, ew}
// ---------------------------------------------------------------------------
__global__ void k_fill(const int* __restrict__ ei,
                       const float* __restrict__ ew) {
    int e = blockIdx.x * blockDim.x + threadIdx.x;
    if (e < NE) {
        int r = ei[e];
        int c = ei[NE + e];
        int pos = atomicAdd(&g_cursor[c], 1);
        g_csr[pos] = make_int2(r | (c << 16), __float_as_int(ew[e]));
    }
}

// Per-node degree + dis (deg = 1 + sum of bucket weights; always >= 1)
__global__ __launch_bounds__(256)
void k_degdis() {
    int node = blockIdx.x * (blockDim.x >> 5) + (threadIdx.x >> 5);
    int lane = threadIdx.x & 31;
    if (node >= NN) return;
    int s = g_off[node], e = g_off[node + 1];
    float sum = 0.0f;
    for (int j = s + lane; j < e; j += 32)
        sum += __int_as_float(g_csr[j].y);
#pragma unroll
    for (int o = 16; o > 0; o >>= 1)
        sum += __shfl_xor_sync(0xFFFFFFFFu, sum, o);
    if (lane == 0) g_dis[node] = rsqrtf(1.0f + sum);
}

// ---------------------------------------------------------------------------
// Tensor GEMM, chunked 3-product split: per 32-col chunk of x (read ONCE),
// build Ahi/Alo bf16 tiles in regs->smem, B tile = [Whi_k; Wlo_k] (64 rows),
// accumulate Ahi*Whi + Ahi*Wlo + Alo*Whi in fp32.
// ---------------------------------------------------------------------------
#define GM 128
#define GK 32
#define NCH (INC / GK)      // 8 chunks
#define ASTR 40             // bf16 units (80B row stride: ldmatrix conflict-free)
#define BSTR 136            // (272B row stride)

#define AHI_OFF 0                          // [2][GM*ASTR] bf16
#define ALO_OFF (2 * GM * ASTR)            // [2][GM*ASTR]
#define B_OFF   (4 * GM * ASTR)            // [2][64*BSTR]
#define SMEM_ELEMS (4 * GM * ASTR + 2 * 64 * BSTR)
#define SMEM_BYTES (SMEM_ELEMS * 2)

__device__ __forceinline__ void cp16(void* s, const void* g) {
    uint32_t sa = (uint32_t)__cvta_generic_to_shared(s);
    asm volatile("cp.async.cg.shared.global [%0], [%1], 16;\n" :: "r"(sa), "l"(g));
}
__device__ __forceinline__ void ldm_x4(uint32_t* r, uint32_t a) {
    asm volatile("ldmatrix.sync.aligned.m8n8.x4.shared.b16 {%0,%1,%2,%3}, [%4];"
                 : "=r"(r[0]), "=r"(r[1]), "=r"(r[2]), "=r"(r[3]) : "r"(a));
}
__device__ __forceinline__ void ldm_x4t(uint32_t* r, uint32_t a) {
    asm volatile("ldmatrix.sync.aligned.m8n8.x4.trans.shared.b16 {%0,%1,%2,%3}, [%4];"
                 : "=r"(r[0]), "=r"(r[1]), "=r"(r[2]), "=r"(r[3]) : "r"(a));
}
__device__ __forceinline__ void mma16816(float* c, const uint32_t* a, const uint32_t* b) {
    asm volatile("mma.sync.aligned.m16n8k16.row.col.f32.bf16.bf16.f32 "
                 "{%0,%1,%2,%3}, {%4,%5,%6,%7}, {%8,%9}, {%0,%1,%2,%3};"
                 : "+f"(c[0]), "+f"(c[1]), "+f"(c[2]), "+f"(c[3])
                 : "r"(a[0]), "r"(a[1]), "r"(a[2]), "r"(a[3]), "r"(b[0]), "r"(b[1]));
}

__device__ __forceinline__ uint2 pack_hi(float4 v) {
    __nv_bfloat16 h0 = __float2bfloat16(v.x), h1 = __float2bfloat16(v.y);
    __nv_bfloat16 h2 = __float2bfloat16(v.z), h3 = __float2bfloat16(v.w);
    uint2 p;
    p.x = ((uint32_t)__bfloat16_as_ushort(h1) << 16) | __bfloat16_as_ushort(h0);
    p.y = ((uint32_t)__bfloat16_as_ushort(h3) << 16) | __bfloat16_as_ushort(h2);
    return p;
}
__device__ __forceinline__ uint2 pack_lo(float4 v) {
    __nv_bfloat16 h0 = __float2bfloat16(v.x), h1 = __float2bfloat16(v.y);
    __nv_bfloat16 h2 = __float2bfloat16(v.z), h3 = __float2bfloat16(v.w);
    __nv_bfloat16 l0 = __float2bfloat16(v.x - __bfloat162float(h0));
    __nv_bfloat16 l1 = __float2bfloat16(v.y - __bfloat162float(h1));
    __nv_bfloat16 l2 = __float2bfloat16(v.z - __bfloat162float(h2));
    __nv_bfloat16 l3 = __float2bfloat16(v.w - __bfloat162float(h3));
    uint2 p;
    p.x = ((uint32_t)__bfloat16_as_ushort(l1) << 16) | __bfloat16_as_ushort(l0);
    p.y = ((uint32_t)__bfloat16_as_ushort(l3) << 16) | __bfloat16_as_ushort(l2);
    return p;
}

__global__ __launch_bounds__(256, 2)
void k_gemm_mma(const float* __restrict__ x) {
    extern __shared__ __nv_bfloat16 smem[];
    __nv_bfloat16* Ahi = smem + AHI_OFF;   // [2][GM*ASTR]
    __nv_bfloat16* Alo = smem + ALO_OFF;   // [2][GM*ASTR]
    __nv_bfloat16* Bs  = smem + B_OFF;     // [2][64*BSTR]

    int tid = threadIdx.x;
    int wid = tid >> 5, lane = tid & 31;
    int wm = wid >> 1, wn = wid & 1;       // 4x2 warps: 32 rows x 64 cols
    int rowBase = blockIdx.x * GM;

    float acc[2][8][4];
#pragma unroll
    for (int i = 0; i < 2; i++)
#pragma unroll
        for (int j = 0; j < 8; j++)
#pragma unroll
            for (int q = 0; q < 4; q++) acc[i][j][q] = 0.0f;

    float4 xstage[4];

    auto ldx = [&](int c) {
        int xcol = c * GK;
#pragma unroll
        for (int l = 0; l < 4; l++) {
            int idx = tid + l * 256;      // 0..1023
            int r  = idx >> 3;            // 128 rows
            int c8 = idx & 7;             // 8 float4 per row
            int gr = rowBase + r;
            float4 v = make_float4(0.f, 0.f, 0.f, 0.f);
            if (gr < NN)
                v = *reinterpret_cast<const float4*>(&x[(size_t)gr * INC + xcol + c8 * 4]);
            xstage[l] = v;
        }
    };
    auto stx = [&](int buf) {
#pragma unroll
        for (int l = 0; l < 4; l++) {
            int idx = tid + l * 256;
            int r  = idx >> 3;
            int c8 = idx & 7;
            *reinterpret_cast<uint2*>(&Ahi[buf * GM * ASTR + r * ASTR + c8 * 4]) =
                pack_hi(xstage[l]);
            *reinterpret_cast<uint2*>(&Alo[buf * GM * ASTR + r * ASTR + c8 * 4]) =
                pack_lo(xstage[l]);
        }
    };
    auto ldb = [&](int c, int buf) {
        int kk = c * GK;
#pragma unroll
        for (int l = 0; l < 4; l++) {
            int idx = tid + l * 256;      // 0..1023
            int kr = idx >> 4;            // 64 rows (0..31 hi, 32..63 lo)
            int cq = idx & 15;            // 16 chunks of 8 bf16
            int srow = (kr < 32) ? (kk + kr) : (256 + kk + (kr - 32));
            cp16(&Bs[buf * 64 * BSTR + kr * BSTR + cq * 8],
                 &g_wcat[(size_t)srow * 128 + cq * 8]);
        }
        asm volatile("cp.async.commit_group;\n");
    };

    ldx(0); ldb(0, 0); stx(0);
    asm volatile("cp.async.wait_group 0;\n");
    __syncthreads();

    for (int c = 0; c < NCH; c++) {
        int cur = c & 1, nxt = cur ^ 1;
        bool more = (c + 1 < NCH);
        if (more) { ldx(c + 1); ldb(c + 1, nxt); }

        uint32_t ahib = (uint32_t)__cvta_generic_to_shared(&Ahi[cur * GM * ASTR]);
        uint32_t alob = (uint32_t)__cvta_generic_to_shared(&Alo[cur * GM * ASTR]);
        uint32_t bb   = (uint32_t)__cvta_generic_to_shared(&Bs[cur * 64 * BSTR]);
        int lr = lane & 15, lc = (lane >> 4) * 8;

#pragma unroll
        for (int ks = 0; ks < 2; ks++) {
            int kb = ks * 16;
            uint32_t af[2][4], bf[4][4];

            // pass 1: Ahi x Whi
#pragma unroll
            for (int mt = 0; mt < 2; mt++)
                ldm_x4(af[mt], ahib + ((wm * 32 + mt * 16 + lr) * ASTR + kb + lc) * 2);
#pragma unroll
            for (int nt = 0; nt < 4; nt++)
                ldm_x4t(bf[nt], bb + ((kb + lr) * BSTR + wn * 64 + nt * 16 + lc) * 2);
#pragma unroll
            for (int mt = 0; mt < 2; mt++)
#pragma unroll
                for (int n8 = 0; n8 < 8; n8++)
                    mma16816(acc[mt][n8], af[mt], &bf[n8 >> 1][(n8 & 1) * 2]);

            // pass 2: Ahi x Wlo (rows 32..63 of B tile)
#pragma unroll
            for (int nt = 0; nt < 4; nt++)
                ldm_x4t(bf[nt], bb + ((32 + kb + lr) * BSTR + wn * 64 + nt * 16 + lc) * 2);
#pragma unroll
            for (int mt = 0; mt < 2; mt++)
#pragma unroll
                for (int n8 = 0; n8 < 8; n8++)
                    mma16816(acc[mt][n8], af[mt], &bf[n8 >> 1][(n8 & 1) * 2]);

            // pass 3: Alo x Whi
#pragma unroll
            for (int mt = 0; mt < 2; mt++)
                ldm_x4(af[mt], alob + ((wm * 32 + mt * 16 + lr) * ASTR + kb + lc) * 2);
#pragma unroll
            for (int nt = 0; nt < 4; nt++)
                ldm_x4t(bf[nt], bb + ((kb + lr) * BSTR + wn * 64 + nt * 16 + lc) * 2);
#pragma unroll
            for (int mt = 0; mt < 2; mt++)
#pragma unroll
                for (int n8 = 0; n8 < 8; n8++)
                    mma16816(acc[mt][n8], af[mt], &bf[n8 >> 1][(n8 & 1) * 2]);
        }

        if (more) {
            stx(nxt);
            asm volatile("cp.async.wait_group 0;\n");
        }
        __syncthreads();
    }

    // Epilogue: write g_h
    int r = lane >> 2, cq = lane & 3;
#pragma unroll
    for (int mt = 0; mt < 2; mt++) {
        int row0 = rowBase + wm * 32 + mt * 16 + r;
        int row1 = row0 + 8;
#pragma unroll
        for (int n8 = 0; n8 < 8; n8++) {
            int col = wn * 64 + n8 * 8 + cq * 2;
            if (row0 < NN)
                *reinterpret_cast<float2*>(&g_h[(size_t)row0 * HC + col]) =
                    make_float2(acc[mt][n8][0], acc[mt][n8][1]);
            if (row1 < NN)
                *reinterpret_cast<float2*>(&g_h[(size_t)row1 * HC + col]) =
                    make_float2(acc[mt][n8][2], acc[mt][n8][3]);
        }
    }
}

// ---------------------------------------------------------------------------
// Aggregate: warp per destination node. Self-loop + CSR gather (norm computed
// inline: dis[r]*ew*dis[c]) + bias + PReLU.
// ---------------------------------------------------------------------------
__global__ __launch_bounds__(256)
void k_agg(float* __restrict__ out, const float* __restrict__ b,
           const float* __restrict__ alpha) {
    int node = blockIdx.x * (blockDim.x >> 5) + (threadIdx.x >> 5);
    int lane = threadIdx.x & 31;
    if (node >= NN) return;

    int s = g_off[node];
    int e = g_off[node + 1];

    float dc = g_dis[node];
    float s2 = dc * dc;
    float4 own = *reinterpret_cast<const float4*>(&g_h[(size_t)node * HC + lane * 4]);
    float4 bb  = *reinterpret_cast<const float4*>(&b[lane * 4]);
    float4 acc = make_float4(fmaf(own.x, s2, bb.x), fmaf(own.y, s2, bb.y),
                             fmaf(own.z, s2, bb.z), fmaf(own.w, s2, bb.w));

    int j = s;
    for (; j + 1 < e; j += 2) {
        int2 e0 = g_csr[j];
        int2 e1 = g_csr[j + 1];
        int r0 = e0.x & 0xFFFF, r1 = e1.x & 0xFFFF;
        float n0 = g_dis[r0] * __int_as_float(e0.y) * dc;
        float n1 = g_dis[r1] * __int_as_float(e1.y) * dc;
        float4 v0 = *reinterpret_cast<const float4*>(&g_h[(size_t)r0 * HC + lane * 4]);
        float4 v1 = *reinterpret_cast<const float4*>(&g_h[(size_t)r1 * HC + lane * 4]);
        acc.x = fmaf(v0.x, n0, acc.x); acc.y = fmaf(v0.y, n0, acc.y);
        acc.z = fmaf(v0.z, n0, acc.z); acc.w = fmaf(v0.w, n0, acc.w);
        acc.x = fmaf(v1.x, n1, acc.x); acc.y = fmaf(v1.y, n1, acc.y);
        acc.z = fmaf(v1.z, n1, acc.z); acc.w = fmaf(v1.w, n1, acc.w);
    }
    if (j < e) {
        int2 e0 = g_csr[j];
        int r0 = e0.x & 0xFFFF;
        float n0 = g_dis[r0] * __int_as_float(e0.y) * dc;
        float4 v0 = *reinterpret_cast<const float4*>(&g_h[(size_t)r0 * HC + lane * 4]);
        acc.x = fmaf(v0.x, n0, acc.x); acc.y = fmaf(v0.y, n0, acc.y);
        acc.z = fmaf(v0.z, n0, acc.z); acc.w = fmaf(v0.w, n0, acc.w);
    }

    float4 aa = *reinterpret_cast<const float4*>(&alpha[lane * 4]);
    acc.x = acc.x >= 0.f ? acc.x : aa.x * acc.x;
    acc.y = acc.y >= 0.f ? acc.y : aa.y * acc.y;
    acc.z = acc.z >= 0.f ? acc.z : aa.z * acc.z;
    acc.w = acc.w >= 0.f ? acc.w : aa.w * acc.w;
    *reinterpret_cast<float4*>(&out[(size_t)node * HC + lane * 4]) = acc;
}

// ---------------------------------------------------------------------------
extern "C" void kernel_launch(void* const* d_in, const int* in_sizes, int n_in,
                              void* d_out, int out_size) {
    const float* x  = (const float*)d_in[0];
    const int*   ei = (const int*)d_in[1];     // int32 (JAX x64-disabled downcast)
    const float* ew = (const float*)d_in[2];
    const float* W  = (const float*)d_in[3];
    const float* b  = (const float*)d_in[4];
    const float* al = (const float*)d_in[5];
    float* out = (float*)d_out;

    static bool smem_set = false;
    if (!smem_set) {
        cudaFuncSetAttribute(k_gemm_mma,
                             cudaFuncAttributeMaxDynamicSharedMemorySize, SMEM_BYTES);
        smem_set = true;
    }

    k_wcat<<<(512 * 128 + 255) / 256, 256>>>(W);
    k_cnt_init<<<(NN + 255) / 256, 256>>>();
    k_count<<<(NE + 255) / 256, 256>>>(ei);
    k_scan_blk<<<NBLK, SCAN_B>>>();
    k_scan_top<<<1, 32>>>();
    k_scan_add<<<NBLK, SCAN_B>>>();
    k_fill<<<(NE + 255) / 256, 256>>>(ei, ew);
    k_degdis<<<(NN * 32 + 255) / 256, 256>>>();
    k_gemm_mma<<<NROWS_PAD / GM, 256, SMEM_BYTES>>>(x);
    k_agg<<<(NN * 32 + 255) / 256, 256>>>(out, b, al);
}